// round 1
// baseline (speedup 1.0000x reference)
#include <cuda_runtime.h>
#include <cstdint>

typedef unsigned long long ull;

#define SEQ    96
#define NHEAD  8
#define DHEAD  32
#define DMOD   256
#define NBATCH 1024
#define MTOT   (NBATCH*SEQ)   // 98304
#define NDIAG  33             // window +-16 -> 33 allowed keys per query

// ---------------- scratch (static device globals: allocation-free) ----------
__device__ float g_q[NBATCH*NHEAD*SEQ*DHEAD];   // [n][h][l][c]
__device__ float g_k[NBATCH*NHEAD*SEQ*DHEAD];
__device__ float g_v[NBATCH*NHEAD*SEQ*DHEAD];
__device__ float g_ao[MTOT*DMOD];               // [n*96+l][h*32+c]

// ---------------- packed fp32x2 helpers (sm_103a) ----------------
__device__ __forceinline__ ull pack2(float x, float y) {
    ull r; asm("mov.b64 %0, {%1,%2};" : "=l"(r) : "f"(x), "f"(y)); return r;
}
__device__ __forceinline__ void ffma2(ull &d, ull a, ull b) {
    asm("fma.rn.f32x2 %0, %1, %2, %0;" : "+l"(d) : "l"(a), "l"(b));
}
__device__ __forceinline__ float2 unpack2(ull v) {
    float2 f; asm("mov.b64 {%0,%1}, %2;" : "=f"(f.x), "=f"(f.y) : "l"(v)); return f;
}

// ---------------- GEMM: C[M,256-chunk] = A[M,256] @ W[256,256] --------------
// QKV=1: by in [0,6): selects Wq/Wk/Wv and 128-col half; epilogue scatters to
//        g_q/g_k/g_v in [n][h][l][c] layout.
// QKV=0: A = g_ao, W = Wo, writes d_out row-major.
template<int QKV>
__global__ void __launch_bounds__(256, 2) gemm_kernel(
    const float* __restrict__ A,
    const float* __restrict__ W0, const float* __restrict__ W1,
    const float* __restrict__ W2,
    float* __restrict__ Cout)
{
    __shared__ float As[16][128];   // transposed: As[k][m]
    __shared__ float Bs[16][128];   // Bs[k][n]

    const int by = blockIdx.y;
    const float* W;
    float* dst;
    int ncol0;
    if (QKV) {
        if (by < 2)      { W = W0; dst = g_q; }
        else if (by < 4) { W = W1; dst = g_k; }
        else             { W = W2; dst = g_v; }
        ncol0 = (by & 1) * 128;
    } else {
        W = W0; dst = Cout; ncol0 = by * 128;
    }
    const float* Abase = QKV ? A : (const float*)g_ao;

    const int m0  = blockIdx.x * 128;
    const int tid = threadIdx.x;
    const int tx  = tid & 15;
    const int ty  = tid >> 4;

    const int arow = tid >> 1;          // 0..127
    const int acol = (tid & 1) * 8;     // 0 or 8
    const int brow = tid >> 4;          // 0..15
    const int bcol = (tid & 15) * 4;    // 0..60

    const float* Ap = Abase + (size_t)(m0 + arow) * DMOD + acol;
    const float* Bp = W + (size_t)brow * DMOD + ncol0 + bcol;

    ull acc[8][4];
    #pragma unroll
    for (int i = 0; i < 8; i++)
        #pragma unroll
        for (int j = 0; j < 4; j++) acc[i][j] = 0ull;

    for (int k0 = 0; k0 < DMOD; k0 += 16) {
        float4 av0 = *(const float4*)(Ap + k0);
        float4 av1 = *(const float4*)(Ap + k0 + 4);
        float4 bv0 = *(const float4*)(Bp + (size_t)k0 * DMOD);
        float4 bv1 = *(const float4*)(Bp + (size_t)k0 * DMOD + 64);

        As[acol + 0][arow] = av0.x;
        As[acol + 1][arow] = av0.y;
        As[acol + 2][arow] = av0.z;
        As[acol + 3][arow] = av0.w;
        As[acol + 4][arow] = av1.x;
        As[acol + 5][arow] = av1.y;
        As[acol + 6][arow] = av1.z;
        As[acol + 7][arow] = av1.w;
        *(float4*)&Bs[brow][bcol]      = bv0;
        *(float4*)&Bs[brow][bcol + 64] = bv1;
        __syncthreads();

        #pragma unroll
        for (int kk = 0; kk < 16; kk++) {
            float4 a0 = *(const float4*)&As[kk][ty * 4];
            float4 a1 = *(const float4*)&As[kk][64 + ty * 4];
            float4 b0 = *(const float4*)&Bs[kk][tx * 4];
            float4 b1 = *(const float4*)&Bs[kk][64 + tx * 4];
            ull aa[8] = { pack2(a0.x,a0.x), pack2(a0.y,a0.y),
                          pack2(a0.z,a0.z), pack2(a0.w,a0.w),
                          pack2(a1.x,a1.x), pack2(a1.y,a1.y),
                          pack2(a1.z,a1.z), pack2(a1.w,a1.w) };
            ull bb[4] = { pack2(b0.x,b0.y), pack2(b0.z,b0.w),
                          pack2(b1.x,b1.y), pack2(b1.z,b1.w) };
            #pragma unroll
            for (int i = 0; i < 8; i++)
                #pragma unroll
                for (int j = 0; j < 4; j++)
                    ffma2(acc[i][j], aa[i], bb[j]);
        }
        __syncthreads();
    }

    // epilogue
    #pragma unroll
    for (int i = 0; i < 8; i++) {
        const int m = m0 + ((i < 4) ? (ty * 4 + i) : (64 + ty * 4 + (i - 4)));
        #pragma unroll
        for (int j = 0; j < 4; j++) {
            const int colL = ncol0 + ((j < 2) ? (tx * 4 + 2 * j)
                                              : (64 + tx * 4 + 2 * (j - 2)));
            float2 v = unpack2(acc[i][j]);
            if (QKV) {
                const int n = m / SEQ, l = m % SEQ;
                const int h = colL >> 5, c = colL & 31;
                float* p = dst + ((((size_t)n * NHEAD + h) * SEQ + l) * DHEAD + c);
                *(float2*)p = v;     // c even, pair stays within one head
            } else {
                *(float2*)(dst + (size_t)m * DMOD + colL) = v;
            }
        }
    }
}

// ---------------- banded attention: one block per (n,h) --------------------
__global__ void __launch_bounds__(96) attn_kernel(const float* __restrict__ rel_bias)
{
    const int nh = blockIdx.x;          // n*8 + h
    const int h  = nh & 7;
    const int n  = nh >> 3;

    __shared__ __align__(16) float ks[SEQ][34];   // stride 34: 8B-aligned rows, no LDS.64 conflicts
    __shared__ __align__(16) float vs[SEQ][34];
    __shared__ float sbias[NDIAG];

    const int tid = threadIdx.x;        // query index i
    const float* kg = g_k + (size_t)nh * (SEQ * DHEAD);
    const float* vg = g_v + (size_t)nh * (SEQ * DHEAD);

    for (int idx = tid; idx < SEQ * DHEAD; idx += 96) {
        const int r = idx >> 5, c = idx & 31;
        ks[r][c] = kg[idx];
        vs[r][c] = vg[idx];
    }
    if (tid < NDIAG) {
        const int dd  = tid - 16;             // offset j-i in [-16,16]
        const int rel = (96 - dd) % 96;       // (i-j) mod 96, nonneg since dd<=16
        sbias[tid] = rel_bias[h * 96 + rel];
    }
    __syncthreads();

    const int i = tid;
    const float* qg = g_q + (size_t)nh * (SEQ * DHEAD) + (size_t)i * DHEAD;
    float q[32];
    #pragma unroll
    for (int c4 = 0; c4 < 8; c4++) {
        float4 t = *(const float4*)(qg + c4 * 4);
        q[c4*4+0] = t.x; q[c4*4+1] = t.y; q[c4*4+2] = t.z; q[c4*4+3] = t.w;
    }
    ull qq[16];
    #pragma unroll
    for (int t = 0; t < 16; t++) qq[t] = pack2(q[2*t], q[2*t+1]);

    const float scale = 0.17677669529663687f;   // 1/sqrt(32)
    float logit[NDIAG];
    #pragma unroll
    for (int d = 0; d < NDIAG; d++) {
        int j = i + d - 16;
        if (j < 0)   j += 96;
        if (j >= 96) j -= 96;
        const ull* kp = (const ull*)&ks[j][0];
        ull a2 = 0ull;
        #pragma unroll
        for (int t = 0; t < 16; t++) ffma2(a2, qq[t], kp[t]);
        float2 s2 = unpack2(a2);
        logit[d] = (s2.x + s2.y) * scale + sbias[d];
    }

    float mx = logit[0];
    #pragma unroll
    for (int d = 1; d < NDIAG; d++) mx = fmaxf(mx, logit[d]);
    float sum = 0.f;
    #pragma unroll
    for (int d = 0; d < NDIAG; d++) { logit[d] = __expf(logit[d] - mx); sum += logit[d]; }

    ull o2[16];
    #pragma unroll
    for (int t = 0; t < 16; t++) o2[t] = 0ull;
    #pragma unroll
    for (int d = 0; d < NDIAG; d++) {
        int j = i + d - 16;
        if (j < 0)   j += 96;
        if (j >= 96) j -= 96;
        const ull ww = pack2(logit[d], logit[d]);
        const ull* vp = (const ull*)&vs[j][0];
        #pragma unroll
        for (int t = 0; t < 16; t++) ffma2(o2[t], ww, vp[t]);
    }

    const float inv = 1.0f / sum;
    float* og = g_ao + ((size_t)n * SEQ + i) * DMOD + h * DHEAD;
    #pragma unroll
    for (int t = 0; t < 16; t++) {
        float2 v = unpack2(o2[t]);
        float2 r; r.x = v.x * inv; r.y = v.y * inv;
        *(float2*)(og + 2 * t) = r;
    }
}

// ---------------- entry point ----------------
extern "C" void kernel_launch(void* const* d_in, const int* in_sizes, int n_in,
                              void* d_out, int out_size)
{
    (void)in_sizes; (void)n_in; (void)out_size;
    const float* Z  = (const float*)d_in[0];
    const float* Wq = (const float*)d_in[1];
    const float* Wk = (const float*)d_in[2];
    const float* Wv = (const float*)d_in[3];
    const float* Wo = (const float*)d_in[4];
    const float* rb = (const float*)d_in[5];
    float* out = (float*)d_out;

    dim3 g1(MTOT / 128, 6);
    gemm_kernel<1><<<g1, 256>>>(Z, Wq, Wk, Wv, nullptr);

    attn_kernel<<<NBATCH * NHEAD, 96>>>(rb);

    dim3 g2(MTOT / 128, 2);
    gemm_kernel<0><<<g2, 256>>>(nullptr, Wo, nullptr, nullptr, out);
}

// round 3
// speedup vs baseline: 1.5648x; 1.5648x over previous
#include <cuda_runtime.h>
#include <cstdint>

typedef unsigned long long ull;

#define SEQ    96
#define NHEAD  8
#define DHEAD  32
#define DMOD   256
#define NBATCH 1024
#define MTOT   (NBATCH*SEQ)   // 98304
#define NDIAG  33

// ---------------- scratch (static device globals: allocation-free) ----------
__device__ float g_q[NBATCH*NHEAD*SEQ*DHEAD];   // [n][h][l][c]
__device__ float g_k[NBATCH*NHEAD*SEQ*DHEAD];
__device__ float g_v[NBATCH*NHEAD*SEQ*DHEAD];
__device__ float g_ao[MTOT*DMOD];               // [n*96+l][h*32+c]

// ---------------- packed fp32x2 helpers (attention) ----------------
__device__ __forceinline__ ull pack2(float x, float y) {
    ull r; asm("mov.b64 %0, {%1,%2};" : "=l"(r) : "f"(x), "f"(y)); return r;
}
__device__ __forceinline__ void ffma2(ull &d, ull a, ull b) {
    asm("fma.rn.f32x2 %0, %1, %2, %0;" : "+l"(d) : "l"(a), "l"(b));
}
__device__ __forceinline__ float2 unpack2(ull v) {
    float2 f; asm("mov.b64 {%0,%1}, %2;" : "=f"(f.x), "=f"(f.y) : "l"(v)); return f;
}

// ---------------- mma helpers (sm_80 baseline ISA, legal on sm_103) --------
__device__ __forceinline__ uint32_t smem_u32(const void* p){
    uint32_t a;
    asm("{ .reg .u64 t; cvta.to.shared.u64 t, %1; cvt.u32.u64 %0, t; }" : "=r"(a) : "l"(p));
    return a;
}
__device__ __forceinline__ void ldsm4(uint32_t& r0, uint32_t& r1, uint32_t& r2,
                                      uint32_t& r3, uint32_t a){
    asm volatile("ldmatrix.sync.aligned.m8n8.x4.shared.b16 {%0,%1,%2,%3}, [%4];"
        : "=r"(r0), "=r"(r1), "=r"(r2), "=r"(r3) : "r"(a));
}
__device__ __forceinline__ void mma_bf16(float* c, const uint32_t* a,
                                         uint32_t b0, uint32_t b1){
    asm volatile("mma.sync.aligned.m16n8k16.row.col.f32.bf16.bf16.f32 "
        "{%0,%1,%2,%3}, {%4,%5,%6,%7}, {%8,%9}, {%0,%1,%2,%3};"
        : "+f"(c[0]), "+f"(c[1]), "+f"(c[2]), "+f"(c[3])
        : "r"(a[0]), "r"(a[1]), "r"(a[2]), "r"(a[3]), "r"(b0), "r"(b1));
}
// split pair (x,y) -> packed bf16x2 hi and lo;  x in low half, y in high half
__device__ __forceinline__ void bsplit2(float x, float y, uint32_t& h2, uint32_t& l2){
    asm("cvt.rn.bf16x2.f32 %0, %1, %2;" : "=r"(h2) : "f"(y), "f"(x));
    float hx = __uint_as_float(h2 << 16);
    float hy = __uint_as_float(h2 & 0xffff0000u);
    float rx = x - hx;       // exact
    float ry = y - hy;       // exact
    asm("cvt.rn.bf16x2.f32 %0, %1, %2;" : "=r"(l2) : "f"(ry), "f"(rx));
}
__device__ __forceinline__ void sts128(uint32_t a, uint32_t r0, uint32_t r1,
                                       uint32_t r2, uint32_t r3){
    asm volatile("st.shared.v4.b32 [%0], {%1,%2,%3,%4};"
        :: "r"(a), "r"(r0), "r"(r1), "r"(r2), "r"(r3) : "memory");
}

// SMEM layout per stage (bf16 tiles, 128 rows x 32 k, rows padded to 80B):
#define ROWB   80
#define SA_H   0
#define SA_L   10240
#define SB_H   20480
#define SB_L   30720
#define STAGE  40960
#define SMEMB  (2*STAGE)     // 81920

// ---------------- bf16x3 tensor-core GEMM: C[M,256] = A[M,256] @ W[256,256] --
// QKV=1: blockIdx.z selects Wq/Wk/Wv; epilogue scatters to g_q/g_k/g_v.
// QKV=0: W = Wq arg, writes Cout row-major.
template<int QKV>
__global__ void __launch_bounds__(256, 2) gemm_mma(
    const float* __restrict__ Ain,
    const float* __restrict__ W0, const float* __restrict__ W1,
    const float* __restrict__ W2,
    float* __restrict__ Cout)
{
    extern __shared__ __align__(128) char smem[];
    const uint32_t sb = smem_u32(smem);
    const int tid  = threadIdx.x;
    const int lane = tid & 31;
    const int wid  = tid >> 5;

    const float* W; float* dst;
    if (QKV) {
        const int z = blockIdx.z;
        W   = (z == 0) ? W0  : (z == 1) ? W1  : W2;
        dst = (z == 0) ? g_q : (z == 1) ? g_k : g_v;
    } else { W = W0; dst = Cout; }
    const float* Ab = QKV ? Ain : (const float*)g_ao;
    const int m0 = blockIdx.x * 128;
    const int n0 = blockIdx.y * 128;

    // ---- loader mapping: 2 threads per row, 16 k each ----
    const int lrow = tid >> 1;            // 0..127
    const int lkh  = (tid & 1) << 4;      // 0 or 16
    const float* gA = Ab + (size_t)(m0 + lrow) * DMOD + lkh;
    const float* gB = W  + (size_t)lkh * DMOD + n0 + lrow;
    const uint32_t offAB = (uint32_t)lrow * ROWB + (uint32_t)lkh * 2;

    // ---- compute mapping ----
    const int mW = (wid & 1) * 64;
    const int nW = (wid >> 1) * 32;
    const int q  = lane >> 3;
    const int rl = lane & 7;
    const uint32_t aOff = (uint32_t)(mW + (q & 1) * 8 + rl) * ROWB + (uint32_t)((q >> 1) * 16);
    const uint32_t bOff = (uint32_t)(nW + (q >> 1) * 8 + rl) * ROWB + (uint32_t)((q & 1) * 16);

    float acc[4][4][4];
    #pragma unroll
    for (int mi = 0; mi < 4; mi++)
        #pragma unroll
        for (int ni = 0; ni < 4; ni++)
            #pragma unroll
            for (int t = 0; t < 4; t++) acc[mi][ni][t] = 0.f;

    float fa[16], fb[16];

    // ---- prologue: chunk 0 -> buffer 0 ----
    {
        const float* pa = gA;
        *(float4*)(fa + 0)  = *(const float4*)(pa + 0);
        *(float4*)(fa + 4)  = *(const float4*)(pa + 4);
        *(float4*)(fa + 8)  = *(const float4*)(pa + 8);
        *(float4*)(fa + 12) = *(const float4*)(pa + 12);
        const float* pb = gB;
        #pragma unroll
        for (int i = 0; i < 16; i++) fb[i] = pb[(size_t)i * DMOD];

        uint32_t h[8], l[8];
        #pragma unroll
        for (int i = 0; i < 8; i++) bsplit2(fa[2*i], fa[2*i+1], h[i], l[i]);
        sts128(sb + SA_H + offAB,      h[0], h[1], h[2], h[3]);
        sts128(sb + SA_H + offAB + 16, h[4], h[5], h[6], h[7]);
        sts128(sb + SA_L + offAB,      l[0], l[1], l[2], l[3]);
        sts128(sb + SA_L + offAB + 16, l[4], l[5], l[6], l[7]);
        #pragma unroll
        for (int i = 0; i < 8; i++) bsplit2(fb[2*i], fb[2*i+1], h[i], l[i]);
        sts128(sb + SB_H + offAB,      h[0], h[1], h[2], h[3]);
        sts128(sb + SB_H + offAB + 16, h[4], h[5], h[6], h[7]);
        sts128(sb + SB_L + offAB,      l[0], l[1], l[2], l[3]);
        sts128(sb + SB_L + offAB + 16, l[4], l[5], l[6], l[7]);
    }
    __syncthreads();

    #pragma unroll 1
    for (int c = 0; c < 8; c++) {
        // ---- prefetch + split + store chunk c+1 into the other buffer ----
        if (c < 7) {
            const uint32_t sB = sb + (uint32_t)((c + 1) & 1) * STAGE;
            const float* pa = gA + (c + 1) * 32;
            *(float4*)(fa + 0)  = *(const float4*)(pa + 0);
            *(float4*)(fa + 4)  = *(const float4*)(pa + 4);
            *(float4*)(fa + 8)  = *(const float4*)(pa + 8);
            *(float4*)(fa + 12) = *(const float4*)(pa + 12);
            const float* pb = gB + (size_t)(c + 1) * 32 * DMOD;
            #pragma unroll
            for (int i = 0; i < 16; i++) fb[i] = pb[(size_t)i * DMOD];

            uint32_t h[8], l[8];
            #pragma unroll
            for (int i = 0; i < 8; i++) bsplit2(fa[2*i], fa[2*i+1], h[i], l[i]);
            sts128(sB + SA_H + offAB,      h[0], h[1], h[2], h[3]);
            sts128(sB + SA_H + offAB + 16, h[4], h[5], h[6], h[7]);
            sts128(sB + SA_L + offAB,      l[0], l[1], l[2], l[3]);
            sts128(sB + SA_L + offAB + 16, l[4], l[5], l[6], l[7]);
            #pragma unroll
            for (int i = 0; i < 8; i++) bsplit2(fb[2*i], fb[2*i+1], h[i], l[i]);
            sts128(sB + SB_H + offAB,      h[0], h[1], h[2], h[3]);
            sts128(sB + SB_H + offAB + 16, h[4], h[5], h[6], h[7]);
            sts128(sB + SB_L + offAB,      l[0], l[1], l[2], l[3]);
            sts128(sB + SB_L + offAB + 16, l[4], l[5], l[6], l[7]);
        }

        // ---- compute chunk c ----
        {
            const uint32_t sBuf = sb + (uint32_t)(c & 1) * STAGE;
            const uint32_t aH = sBuf + SA_H + aOff;
            const uint32_t aL = sBuf + SA_L + aOff;
            const uint32_t bH = sBuf + SB_H + bOff;
            const uint32_t bL = sBuf + SB_L + bOff;
            #pragma unroll
            for (int k16 = 0; k16 < 2; k16++) {
                const uint32_t ko = (uint32_t)k16 * 32;
                uint32_t BH[8], BL[8], A[16];
                ldsm4(BH[0], BH[1], BH[2], BH[3], bH + ko);
                ldsm4(BH[4], BH[5], BH[6], BH[7], bH + ko + 16 * ROWB);
                ldsm4(BL[0], BL[1], BL[2], BL[3], bL + ko);
                ldsm4(BL[4], BL[5], BL[6], BL[7], bL + ko + 16 * ROWB);
                #pragma unroll
                for (int mi = 0; mi < 4; mi++)
                    ldsm4(A[4*mi+0], A[4*mi+1], A[4*mi+2], A[4*mi+3],
                          aH + ko + (uint32_t)mi * 16 * ROWB);
                #pragma unroll
                for (int mi = 0; mi < 4; mi++)
                    #pragma unroll
                    for (int ni = 0; ni < 4; ni++)
                        mma_bf16(acc[mi][ni], &A[4*mi], BH[2*ni], BH[2*ni+1]);
                #pragma unroll
                for (int mi = 0; mi < 4; mi++)
                    #pragma unroll
                    for (int ni = 0; ni < 4; ni++)
                        mma_bf16(acc[mi][ni], &A[4*mi], BL[2*ni], BL[2*ni+1]);
                #pragma unroll
                for (int mi = 0; mi < 4; mi++)
                    ldsm4(A[4*mi+0], A[4*mi+1], A[4*mi+2], A[4*mi+3],
                          aL + ko + (uint32_t)mi * 16 * ROWB);
                #pragma unroll
                for (int mi = 0; mi < 4; mi++)
                    #pragma unroll
                    for (int ni = 0; ni < 4; ni++)
                        mma_bf16(acc[mi][ni], &A[4*mi], BH[2*ni], BH[2*ni+1]);
            }
        }
        __syncthreads();
    }

    // ---- epilogue ----
    const int r0q = lane >> 2;          // 0..7
    const int c0q = (lane & 3) * 2;     // 0,2,4,6
    #pragma unroll
    for (int mi = 0; mi < 4; mi++) {
        #pragma unroll
        for (int half = 0; half < 2; half++) {
            const int row = m0 + mW + mi * 16 + half * 8 + r0q;
            if (QKV) {
                const int nb = row / SEQ, l = row % SEQ;
                float* base = dst + (((size_t)nb * NHEAD) * SEQ + l) * DHEAD;
                #pragma unroll
                for (int ni = 0; ni < 4; ni++) {
                    const int col = n0 + nW + ni * 8 + c0q;
                    const int h = col >> 5, cc = col & 31;
                    float2 v;
                    v.x = acc[mi][ni][half*2+0];
                    v.y = acc[mi][ni][half*2+1];
                    *(float2*)(base + (size_t)h * (SEQ*DHEAD) + cc) = v;
                }
            } else {
                float* base = dst + (size_t)row * DMOD;
                #pragma unroll
                for (int ni = 0; ni < 4; ni++) {
                    const int col = n0 + nW + ni * 8 + c0q;
                    float2 v;
                    v.x = acc[mi][ni][half*2+0];
                    v.y = acc[mi][ni][half*2+1];
                    *(float2*)(base + col) = v;
                }
            }
        }
    }
}

// ---------------- banded attention: one block per (n,h) --------------------
__global__ void __launch_bounds__(96) attn_kernel(const float* __restrict__ rel_bias)
{
    const int nh = blockIdx.x;          // n*8 + h
    const int h  = nh & 7;
    const int n  = nh >> 3;

    __shared__ __align__(16) float ks[SEQ][34];
    __shared__ __align__(16) float vs[SEQ][34];
    __shared__ float sbias[NDIAG];

    const int tid = threadIdx.x;        // query index i
    const float* kg = g_k + (size_t)nh * (SEQ * DHEAD);
    const float* vg = g_v + (size_t)nh * (SEQ * DHEAD);

    for (int idx = tid; idx < SEQ * DHEAD; idx += 96) {
        const int r = idx >> 5, c = idx & 31;
        ks[r][c] = kg[idx];
        vs[r][c] = vg[idx];
    }
    if (tid < NDIAG) {
        const int dd  = tid - 16;             // offset j-i in [-16,16]
        const int rel = (96 - dd) % 96;       // (i-j) mod 96
        sbias[tid] = rel_bias[h * 96 + rel];
    }
    __syncthreads();

    const int i = tid;
    const float* qg = g_q + (size_t)nh * (SEQ * DHEAD) + (size_t)i * DHEAD;
    float qv[32];
    #pragma unroll
    for (int c4 = 0; c4 < 8; c4++) {
        float4 t = *(const float4*)(qg + c4 * 4);
        qv[c4*4+0] = t.x; qv[c4*4+1] = t.y; qv[c4*4+2] = t.z; qv[c4*4+3] = t.w;
    }
    ull qq[16];
    #pragma unroll
    for (int t = 0; t < 16; t++) qq[t] = pack2(qv[2*t], qv[2*t+1]);

    const float scale = 0.17677669529663687f;   // 1/sqrt(32)
    float logit[NDIAG];
    #pragma unroll
    for (int d = 0; d < NDIAG; d++) {
        int j = i + d - 16;
        if (j < 0)   j += 96;
        if (j >= 96) j -= 96;
        const ull* kp = (const ull*)&ks[j][0];
        ull a2 = 0ull;
        #pragma unroll
        for (int t = 0; t < 16; t++) ffma2(a2, qq[t], kp[t]);
        float2 s2 = unpack2(a2);
        logit[d] = (s2.x + s2.y) * scale + sbias[d];
    }

    float mx = logit[0];
    #pragma unroll
    for (int d = 1; d < NDIAG; d++) mx = fmaxf(mx, logit[d]);
    float sum = 0.f;
    #pragma unroll
    for (int d = 0; d < NDIAG; d++) { logit[d] = __expf(logit[d] - mx); sum += logit[d]; }

    ull o2[16];
    #pragma unroll
    for (int t = 0; t < 16; t++) o2[t] = 0ull;
    #pragma unroll
    for (int d = 0; d < NDIAG; d++) {
        int j = i + d - 16;
        if (j < 0)   j += 96;
        if (j >= 96) j -= 96;
        const ull ww = pack2(logit[d], logit[d]);
        const ull* vp = (const ull*)&vs[j][0];
        #pragma unroll
        for (int t = 0; t < 16; t++) ffma2(o2[t], ww, vp[t]);
    }

    const float inv = 1.0f / sum;
    float* og = g_ao + ((size_t)n * SEQ + i) * DMOD + h * DHEAD;
    #pragma unroll
    for (int t = 0; t < 16; t++) {
        float2 v = unpack2(o2[t]);
        float2 r; r.x = v.x * inv; r.y = v.y * inv;
        *(float2*)(og + 2 * t) = r;
    }
}

// ---------------- entry point ----------------
extern "C" void kernel_launch(void* const* d_in, const int* in_sizes, int n_in,
                              void* d_out, int out_size)
{
    (void)in_sizes; (void)n_in; (void)out_size;
    const float* Z  = (const float*)d_in[0];
    const float* Wq = (const float*)d_in[1];
    const float* Wk = (const float*)d_in[2];
    const float* Wv = (const float*)d_in[3];
    const float* Wo = (const float*)d_in[4];
    const float* rb = (const float*)d_in[5];
    float* out = (float*)d_out;

    cudaFuncSetAttribute(gemm_mma<1>, cudaFuncAttributeMaxDynamicSharedMemorySize, SMEMB);
    cudaFuncSetAttribute(gemm_mma<0>, cudaFuncAttributeMaxDynamicSharedMemorySize, SMEMB);

    dim3 g1(MTOT / 128, 2, 3);
    gemm_mma<1><<<g1, 256, SMEMB>>>(Z, Wq, Wk, Wv, nullptr);

    attn_kernel<<<NBATCH * NHEAD, 96>>>(rb);

    dim3 g2(MTOT / 128, 2, 1);
    gemm_mma<0><<<g2, 256, SMEMB>>>(nullptr, Wo, nullptr, nullptr, out);
}

// round 5
// speedup vs baseline: 1.6193x; 1.0348x over previous
#include <cuda_runtime.h>
#include <cstdint>

typedef unsigned long long ull;

#define SEQ    96
#define NHEAD  8
#define DHEAD  32
#define DMOD   256
#define NBATCH 1024
#define MTOT   (NBATCH*SEQ)   // 98304
#define NDIAG  33

// ---------------- scratch (static device globals) ----------------
__device__ float g_q[NBATCH*NHEAD*SEQ*DHEAD];
__device__ float g_k[NBATCH*NHEAD*SEQ*DHEAD];
__device__ float g_v[NBATCH*NHEAD*SEQ*DHEAD];
__device__ float g_ao[MTOT*DMOD];

// ---------------- helpers ----------------
__device__ __forceinline__ ull pack2(float x, float y) {
    ull r; asm("mov.b64 %0, {%1,%2};" : "=l"(r) : "f"(x), "f"(y)); return r;
}
__device__ __forceinline__ void ffma2(ull &d, ull a, ull b) {
    asm("fma.rn.f32x2 %0, %1, %2, %0;" : "+l"(d) : "l"(a), "l"(b));
}
__device__ __forceinline__ float2 unpack2(ull v) {
    float2 f; asm("mov.b64 {%0,%1}, %2;" : "=f"(f.x), "=f"(f.y) : "l"(v)); return f;
}
__device__ __forceinline__ uint32_t smem_u32(const void* p){
    uint32_t a;
    asm("{ .reg .u64 t; cvta.to.shared.u64 t, %1; cvt.u32.u64 %0, t; }" : "=r"(a) : "l"(p));
    return a;
}
__device__ __forceinline__ void ldsm4(uint32_t& r0, uint32_t& r1, uint32_t& r2,
                                      uint32_t& r3, uint32_t a){
    asm volatile("ldmatrix.sync.aligned.m8n8.x4.shared.b16 {%0,%1,%2,%3}, [%4];"
        : "=r"(r0), "=r"(r1), "=r"(r2), "=r"(r3) : "r"(a));
}
__device__ __forceinline__ void mma_bf16(float* c, const uint32_t* a,
                                         uint32_t b0, uint32_t b1){
    asm volatile("mma.sync.aligned.m16n8k16.row.col.f32.bf16.bf16.f32 "
        "{%0,%1,%2,%3}, {%4,%5,%6,%7}, {%8,%9}, {%0,%1,%2,%3};"
        : "+f"(c[0]), "+f"(c[1]), "+f"(c[2]), "+f"(c[3])
        : "r"(a[0]), "r"(a[1]), "r"(a[2]), "r"(a[3]), "r"(b0), "r"(b1));
}
__device__ __forceinline__ void bsplit2(float x, float y, uint32_t& h2, uint32_t& l2){
    asm("cvt.rn.bf16x2.f32 %0, %1, %2;" : "=r"(h2) : "f"(y), "f"(x));
    float hx = __uint_as_float(h2 << 16);
    float hy = __uint_as_float(h2 & 0xffff0000u);
    float rx = x - hx;
    float ry = y - hy;
    asm("cvt.rn.bf16x2.f32 %0, %1, %2;" : "=r"(l2) : "f"(ry), "f"(rx));
}
__device__ __forceinline__ void sts128(uint32_t a, uint32_t r0, uint32_t r1,
                                       uint32_t r2, uint32_t r3){
    asm volatile("st.shared.v4.b32 [%0], {%1,%2,%3,%4};"
        :: "r"(a), "r"(r0), "r"(r1), "r"(r2), "r"(r3) : "memory");
}

// SMEM stage layout (bf16 tiles, rows padded to 80B):
//  A hi: 128 rows  A lo: 128 rows  B hi: 256 rows  B lo: 256 rows
#define ROWB  80
#define ST_AH 0
#define ST_AL 10240
#define ST_BH 20480
#define ST_BL 40960
#define STG   61440
#define SMEMB (2*STG)   // 122880

// ---------------- bf16x3 tensor-core GEMM: C[128,256] = A[128,256] @ W ------
// QKV=1: blockIdx.y selects Wq/Wk/Wv; epilogue scatters to g_q/g_k/g_v.
// QKV=0: W = W0 (Wo), A = g_ao, writes Cout row-major.
template<int QKV>
__global__ void __launch_bounds__(256, 1) gemm_mma(
    const float* __restrict__ Ain,
    const float* __restrict__ W0, const float* __restrict__ W1,
    const float* __restrict__ W2,
    float* __restrict__ Cout)
{
    extern __shared__ __align__(128) char smem[];
    const uint32_t sb = smem_u32(smem);
    const int tid  = threadIdx.x;
    const int lane = tid & 31;
    const int wid  = tid >> 5;

    const float* W; float* dst;
    if (QKV) {
        const int z = blockIdx.y;
        W   = (z == 0) ? W0  : (z == 1) ? W1  : W2;
        dst = (z == 0) ? g_q : (z == 1) ? g_k : g_v;
    } else { W = W0; dst = Cout; }
    const float* Ab = QKV ? Ain : (const float*)g_ao;
    const int m0 = blockIdx.x * 128;

    // ---- loader mapping ----
    // A: thread -> row (tid&127), k-half 16*(tid>>7)
    const int ar = tid & 127;
    const int ah = (tid >> 7) << 4;
    const float* gA = Ab + (size_t)(m0 + ar) * DMOD + ah;
    const uint32_t aDst = (uint32_t)ar * ROWB + (uint32_t)(ah << 1);
    // B: thread -> n row (tid), all 32 k of the chunk (strided, coalesced across threads)
    const float* gB = W + tid;
    const uint32_t bDst = (uint32_t)tid * ROWB;

    // ---- compute mapping: warp tile 64x64 ----
    const int mW = (wid & 1) * 64;
    const int nW = (wid >> 1) * 64;
    const int q  = lane >> 3;
    const int rl = lane & 7;
    const uint32_t aOff = (uint32_t)(mW + (q & 1) * 8 + rl) * ROWB + (uint32_t)((q >> 1) * 16);
    const uint32_t bOff = (uint32_t)(nW + (q >> 1) * 8 + rl) * ROWB + (uint32_t)((q & 1) * 16);

    float acc[4][8][4];
    #pragma unroll
    for (int mi = 0; mi < 4; mi++)
        #pragma unroll
        for (int ni = 0; ni < 8; ni++)
            #pragma unroll
            for (int t = 0; t < 4; t++) acc[mi][ni][t] = 0.f;

    float fa[16], fb[32];

    // LDG chunk c into registers
    auto ldgA = [&](int c){
        const float* p = gA + c * 32;
        *(float4*)(fa + 0)  = *(const float4*)(p + 0);
        *(float4*)(fa + 4)  = *(const float4*)(p + 4);
        *(float4*)(fa + 8)  = *(const float4*)(p + 8);
        *(float4*)(fa + 12) = *(const float4*)(p + 12);
    };
    auto ldgB = [&](int c){
        const float* p = gB + (size_t)c * 32 * DMOD;
        #pragma unroll
        for (int i = 0; i < 32; i++) fb[i] = p[(size_t)i * DMOD];
    };
    // split regs -> smem buffer
    auto stsAB = [&](uint32_t sBase){
        uint32_t h[16], l[16];
        #pragma unroll
        for (int i = 0; i < 8; i++) bsplit2(fa[2*i], fa[2*i+1], h[i], l[i]);
        sts128(sBase + ST_AH + aDst,      h[0], h[1], h[2], h[3]);
        sts128(sBase + ST_AH + aDst + 16, h[4], h[5], h[6], h[7]);
        sts128(sBase + ST_AL + aDst,      l[0], l[1], l[2], l[3]);
        sts128(sBase + ST_AL + aDst + 16, l[4], l[5], l[6], l[7]);
        #pragma unroll
        for (int i = 0; i < 16; i++) bsplit2(fb[2*i], fb[2*i+1], h[i], l[i]);
        sts128(sBase + ST_BH + bDst,      h[0],  h[1],  h[2],  h[3]);
        sts128(sBase + ST_BH + bDst + 16, h[4],  h[5],  h[6],  h[7]);
        sts128(sBase + ST_BH + bDst + 32, h[8],  h[9],  h[10], h[11]);
        sts128(sBase + ST_BH + bDst + 48, h[12], h[13], h[14], h[15]);
        sts128(sBase + ST_BL + bDst,      l[0],  l[1],  l[2],  l[3]);
        sts128(sBase + ST_BL + bDst + 16, l[4],  l[5],  l[6],  l[7]);
        sts128(sBase + ST_BL + bDst + 32, l[8],  l[9],  l[10], l[11]);
        sts128(sBase + ST_BL + bDst + 48, l[12], l[13], l[14], l[15]);
    };

    // prologue: chunk 0 -> buf0; prefetch chunk 1 into regs
    ldgA(0); ldgB(0);
    stsAB(sb);
    ldgA(1); ldgB(1);
    __syncthreads();

    #pragma unroll 1
    for (int c = 0; c < 8; c++){
        // ---- compute chunk c from buffer c&1 ----
        const uint32_t sBuf = sb + (uint32_t)(c & 1) * STG;
        const uint32_t aH = sBuf + ST_AH + aOff;
        const uint32_t aL = sBuf + ST_AL + aOff;
        const uint32_t bH = sBuf + ST_BH + bOff;
        const uint32_t bL = sBuf + ST_BL + bOff;
        #pragma unroll
        for (int k16 = 0; k16 < 2; k16++){
            const uint32_t ko = (uint32_t)k16 * 32;
            uint32_t A_[16], B_[16], C_[16];
            #pragma unroll
            for (int mi = 0; mi < 4; mi++)
                ldsm4(A_[4*mi], A_[4*mi+1], A_[4*mi+2], A_[4*mi+3],
                      aH + ko + (uint32_t)mi * (16*ROWB));
            #pragma unroll
            for (int j = 0; j < 4; j++)
                ldsm4(B_[4*j], B_[4*j+1], B_[4*j+2], B_[4*j+3],
                      bH + ko + (uint32_t)j * (16*ROWB));
            #pragma unroll
            for (int mi = 0; mi < 4; mi++)
                #pragma unroll
                for (int ni = 0; ni < 8; ni++)
                    mma_bf16(acc[mi][ni], &A_[4*mi], B_[2*ni], B_[2*ni+1]);
            #pragma unroll
            for (int j = 0; j < 4; j++)
                ldsm4(C_[4*j], C_[4*j+1], C_[4*j+2], C_[4*j+3],
                      bL + ko + (uint32_t)j * (16*ROWB));
            #pragma unroll
            for (int mi = 0; mi < 4; mi++)
                #pragma unroll
                for (int ni = 0; ni < 8; ni++)
                    mma_bf16(acc[mi][ni], &A_[4*mi], C_[2*ni], C_[2*ni+1]);
            #pragma unroll
            for (int mi = 0; mi < 4; mi++)
                ldsm4(A_[4*mi], A_[4*mi+1], A_[4*mi+2], A_[4*mi+3],
                      aL + ko + (uint32_t)mi * (16*ROWB));
            #pragma unroll
            for (int mi = 0; mi < 4; mi++)
                #pragma unroll
                for (int ni = 0; ni < 8; ni++)
                    mma_bf16(acc[mi][ni], &A_[4*mi], B_[2*ni], B_[2*ni+1]);
        }
        // ---- store prefetched chunk c+1; start LDG of chunk c+2 ----
        if (c < 7) stsAB(sb + (uint32_t)((c + 1) & 1) * STG);
        if (c < 6) { ldgA(c + 2); ldgB(c + 2); }
        __syncthreads();
    }

    // ---- epilogue ----
    const int r0q = lane >> 2;
    const int c0q = (lane & 3) * 2;
    #pragma unroll
    for (int mi = 0; mi < 4; mi++){
        #pragma unroll
        for (int half = 0; half < 2; half++){
            const int row = m0 + mW + mi * 16 + half * 8 + r0q;
            if (QKV){
                const int nb = row / SEQ, l = row % SEQ;
                float* base = dst + (((size_t)nb * NHEAD) * SEQ + l) * DHEAD;
                #pragma unroll
                for (int ni = 0; ni < 8; ni++){
                    const int col = nW + ni * 8 + c0q;
                    const int h = col >> 5, cc = col & 31;
                    float2 v;
                    v.x = acc[mi][ni][half*2+0];
                    v.y = acc[mi][ni][half*2+1];
                    *(float2*)(base + (size_t)h * (SEQ*DHEAD) + cc) = v;
                }
            } else {
                float* base = dst + (size_t)row * DMOD;
                #pragma unroll
                for (int ni = 0; ni < 8; ni++){
                    const int col = nW + ni * 8 + c0q;
                    float2 v;
                    v.x = acc[mi][ni][half*2+0];
                    v.y = acc[mi][ni][half*2+1];
                    *(float2*)(base + col) = v;
                }
            }
        }
    }
}

// ---------------- banded attention: one block per (n,h) --------------------
__global__ void __launch_bounds__(96) attn_kernel(const float* __restrict__ rel_bias)
{
    const int nh = blockIdx.x;
    const int h  = nh & 7;
    const int n  = nh >> 3;

    __shared__ __align__(16) float ks[SEQ][34];
    __shared__ __align__(16) float vs[SEQ][34];
    __shared__ float sbias[NDIAG];

    const int tid = threadIdx.x;
    const float* kg = g_k + (size_t)nh * (SEQ * DHEAD);
    const float* vg = g_v + (size_t)nh * (SEQ * DHEAD);

    for (int idx = tid; idx < SEQ * DHEAD; idx += 96) {
        const int r = idx >> 5, c = idx & 31;
        ks[r][c] = kg[idx];
        vs[r][c] = vg[idx];
    }
    if (tid < NDIAG) {
        const int dd  = tid - 16;
        const int rel = (96 - dd) % 96;
        sbias[tid] = rel_bias[h * 96 + rel];
    }
    __syncthreads();

    const int i = tid;
    const float* qg = g_q + (size_t)nh * (SEQ * DHEAD) + (size_t)i * DHEAD;
    float qv[32];
    #pragma unroll
    for (int c4 = 0; c4 < 8; c4++) {
        float4 t = *(const float4*)(qg + c4 * 4);
        qv[c4*4+0] = t.x; qv[c4*4+1] = t.y; qv[c4*4+2] = t.z; qv[c4*4+3] = t.w;
    }
    ull qq[16];
    #pragma unroll
    for (int t = 0; t < 16; t++) qq[t] = pack2(qv[2*t], qv[2*t+1]);

    const float scale = 0.17677669529663687f;
    float logit[NDIAG];
    #pragma unroll
    for (int d = 0; d < NDIAG; d++) {
        int j = i + d - 16;
        if (j < 0)   j += 96;
        if (j >= 96) j -= 96;
        const ull* kp = (const ull*)&ks[j][0];
        ull a2 = 0ull;
        #pragma unroll
        for (int t = 0; t < 16; t++) ffma2(a2, qq[t], kp[t]);
        float2 s2 = unpack2(a2);
        logit[d] = (s2.x + s2.y) * scale + sbias[d];
    }

    float mx = logit[0];
    #pragma unroll
    for (int d = 1; d < NDIAG; d++) mx = fmaxf(mx, logit[d]);
    float sum = 0.f;
    #pragma unroll
    for (int d = 0; d < NDIAG; d++) { logit[d] = __expf(logit[d] - mx); sum += logit[d]; }

    ull o2[16];
    #pragma unroll
    for (int t = 0; t < 16; t++) o2[t] = 0ull;
    #pragma unroll
    for (int d = 0; d < NDIAG; d++) {
        int j = i + d - 16;
        if (j < 0)   j += 96;
        if (j >= 96) j -= 96;
        const ull ww = pack2(logit[d], logit[d]);
        const ull* vp = (const ull*)&vs[j][0];
        #pragma unroll
        for (int t = 0; t < 16; t++) ffma2(o2[t], ww, vp[t]);
    }

    const float inv = 1.0f / sum;
    float* og = g_ao + ((size_t)n * SEQ + i) * DMOD + h * DHEAD;
    #pragma unroll
    for (int t = 0; t < 16; t++) {
        float2 v = unpack2(o2[t]);
        float2 r; r.x = v.x * inv; r.y = v.y * inv;
        *(float2*)(og + 2 * t) = r;
    }
}

// ---------------- entry point ----------------
extern "C" void kernel_launch(void* const* d_in, const int* in_sizes, int n_in,
                              void* d_out, int out_size)
{
    (void)in_sizes; (void)n_in; (void)out_size;
    const float* Z  = (const float*)d_in[0];
    const float* Wq = (const float*)d_in[1];
    const float* Wk = (const float*)d_in[2];
    const float* Wv = (const float*)d_in[3];
    const float* Wo = (const float*)d_in[4];
    const float* rb = (const float*)d_in[5];
    float* out = (float*)d_out;

    cudaFuncSetAttribute(gemm_mma<1>, cudaFuncAttributeMaxDynamicSharedMemorySize, SMEMB);
    cudaFuncSetAttribute(gemm_mma<0>, cudaFuncAttributeMaxDynamicSharedMemorySize, SMEMB);

    dim3 g1(MTOT / 128, 3);
    gemm_mma<1><<<g1, 256, SMEMB>>>(Z, Wq, Wk, Wv, nullptr);

    attn_kernel<<<NBATCH * NHEAD, 96>>>(rb);

    dim3 g2(MTOT / 128, 1);
    gemm_mma<0><<<g2, 256, SMEMB>>>(nullptr, Wo, nullptr, nullptr, out);
}